// round 8
// baseline (speedup 1.0000x reference)
#include <cuda_runtime.h>
#include <cstdint>

#define N_DATA 131072
#define DVEC   128
#define NSUB   8
#define DSUB   16
#define KCLUS  256
#define NCB    64
#define PPB    256
#define MAXWORK 640            // worst case 512 + 64 partials = 576

typedef unsigned long long u64;

// ---------------- device scratch ----------------
__device__ float g_xT[(size_t)N_DATA * DVEC];                       // 67 MB x transposed [n][d]
__device__ float g_ckPack[NCB * NSUB * KCLUS * DSUB];               // 8 MB [cb][s][k][d] (decode)
__device__ __align__(16) u64 g_ckPair[(size_t)NCB * NSUB * 128 * DSUB]; // 8 MB pair-packed
__device__ __align__(16) u64 g_cn2[NCB * NSUB * 128];               // (-cn(2p)/2, -cn(2p+1)/2)
__device__ __align__(16) u64 g_selPair[64 * 32 * 2];                // [dstep][pair][2dims]
__device__ u64   g_ln2[32];
__device__ int   g_labels[N_DATA];
__device__ int   g_perm[N_DATA];
__device__ u64   g_codes[N_DATA];
__device__ int   g_hist[NCB];
__device__ int   g_offsets[NCB + 1];
__device__ int   g_cursor[NCB];
__device__ int4  g_worklist[MAXWORK];
__device__ int   g_nwork;

// ---------------- helpers ----------------
__device__ __forceinline__ u64 pk2(float lo, float hi) {
    u64 r; asm("mov.b64 %0, {%1,%2};" : "=l"(r) : "f"(lo), "f"(hi)); return r;
}
__device__ __forceinline__ void unpk2(u64 v, float& lo, float& hi) {
    asm("mov.b64 {%0,%1}, %2;" : "=f"(lo), "=f"(hi) : "l"(v));
}
__device__ __forceinline__ u64 ffma2(u64 a, u64 b, u64 c) {
    u64 d; asm("fma.rn.f32x2 %0, %1, %2, %3;" : "=l"(d) : "l"(a), "l"(b), "l"(c)); return d;
}
__device__ __forceinline__ void cpa16(void* dst, const void* src) {
    unsigned int d = (unsigned int)__cvta_generic_to_shared(dst);
    asm volatile("cp.async.cg.shared.global [%0], [%1], 16;" :: "r"(d), "l"(src));
}
__device__ __forceinline__ void cpa_commit() { asm volatile("cp.async.commit_group;"); }
__device__ __forceinline__ void cpa_wait0()  { asm volatile("cp.async.wait_group 0;"); }

// ---------------- K1: pack codebook + selector (+ zero hist) ----------------
__global__ void k_pack(const float* __restrict__ cb, const float* __restrict__ sel) {
    int bid = blockIdx.x, tid = threadIdx.x;
    if (bid < NCB * NSUB) {
        __shared__ float t[DSUB][KCLUS + 1];
        __shared__ float cnsh[KCLUS];
        const float* src = cb + (size_t)bid * DSUB * KCLUS;
        for (int i = tid; i < DSUB * KCLUS; i += 256) t[i >> 8][i & 255] = src[i];
        __syncthreads();
        int k = tid;
        float v[DSUB]; float cn = 0.f;
        #pragma unroll
        for (int d = 0; d < DSUB; d++) { v[d] = t[d][k]; cn = fmaf(v[d], v[d], cn); }
        float4* dst = (float4*)(g_ckPack + ((size_t)bid * KCLUS + k) * DSUB);
        dst[0] = make_float4(v[0], v[1], v[2], v[3]);
        dst[1] = make_float4(v[4], v[5], v[6], v[7]);
        dst[2] = make_float4(v[8], v[9], v[10], v[11]);
        dst[3] = make_float4(v[12], v[13], v[14], v[15]);
        cnsh[k] = cn;
        __syncthreads();
        if (tid < 128) {
            int p = tid;
            g_cn2[bid * 128 + p] = pk2(-0.5f * cnsh[2 * p], -0.5f * cnsh[2 * p + 1]);
            u64* dp = g_ckPair + ((size_t)bid * 128 + p) * DSUB;
            #pragma unroll
            for (int d = 0; d < DSUB; d++)
                dp[d] = pk2(t[d][2 * p], t[d][2 * p + 1]);
        }
    } else {
        __shared__ float cnselS[NCB];
        if (tid < NCB) {
            g_hist[tid] = 0;                                  // fused k_init
            float s = 0.f;
            for (int d = 0; d < DVEC; d++) { float v = sel[d * NCB + tid]; s = fmaf(v, v, s); }
            cnselS[tid] = s;
        }
        __syncthreads();
        if (tid < 32) g_ln2[tid] = pk2(-0.5f * cnselS[2 * tid], -0.5f * cnselS[2 * tid + 1]);
        for (int i = tid; i < 64 * 32 * 2; i += 256) {
            int ds = i >> 6, r = i & 63, p = r >> 1, j = r & 1, d = 2 * ds + j;
            g_selPair[i] = pk2(sel[d * NCB + 2 * p], sel[d * NCB + 2 * p + 1]);
        }
    }
}

// ---------------- K3: labels + fused xT write ----------------
__global__ void __launch_bounds__(256, 2) k_label(const float* __restrict__ x) {
    __shared__ __align__(16) u64 selS[64 * 32 * 2];  // 32 KB
    __shared__ u64 ln2S[32];
    __shared__ int hS[NCB];
    int tid = threadIdx.x;
    for (int i = tid; i < 2048; i += 256)
        ((ulonglong2*)selS)[i] = ((const ulonglong2*)g_selPair)[i];
    if (tid < 32) ln2S[tid] = g_ln2[tid];
    if (tid < NCB) hS[tid] = 0;
    __syncthreads();

    int n0 = blockIdx.x * 512 + tid;
    int n1 = n0 + 256;
    const float* xc0 = x + n0;
    const float* xc1 = x + n1;

    float best0 = -3.4e38f, best1 = -3.4e38f;
    int bl0 = 0, bl1 = 0;

    for (int q = 0; q < 4; q++) {
        u64 acc0[8], acc1[8];
        #pragma unroll
        for (int p = 0; p < 8; p++) { u64 v = ln2S[q * 8 + p]; acc0[p] = v; acc1[p] = v; }

        for (int c = 0; c < 16; c++) {
            float xr0[8], xr1[8];
            const float* xp0 = xc0 + (size_t)(8 * c) * N_DATA;
            const float* xp1 = xc1 + (size_t)(8 * c) * N_DATA;
            #pragma unroll
            for (int i = 0; i < 8; i++) xr0[i] = xp0[(size_t)i * N_DATA];
            #pragma unroll
            for (int i = 0; i < 8; i++) xr1[i] = xp1[(size_t)i * N_DATA];

            if (q == 0) {
                float4* d0 = (float4*)(g_xT + (size_t)n0 * DVEC + 8 * c);
                float4* d1 = (float4*)(g_xT + (size_t)n1 * DVEC + 8 * c);
                d0[0] = make_float4(xr0[0], xr0[1], xr0[2], xr0[3]);
                d0[1] = make_float4(xr0[4], xr0[5], xr0[6], xr0[7]);
                d1[0] = make_float4(xr1[0], xr1[1], xr1[2], xr1[3]);
                d1[1] = make_float4(xr1[4], xr1[5], xr1[6], xr1[7]);
            }

            #pragma unroll
            for (int i2 = 0; i2 < 4; i2++) {
                int ds = 4 * c + i2;
                u64 a00 = pk2(xr0[2 * i2], xr0[2 * i2]);
                u64 a01 = pk2(xr0[2 * i2 + 1], xr0[2 * i2 + 1]);
                u64 a10 = pk2(xr1[2 * i2], xr1[2 * i2]);
                u64 a11 = pk2(xr1[2 * i2 + 1], xr1[2 * i2 + 1]);
                const ulonglong2* row = (const ulonglong2*)(selS + ds * 64 + q * 16);
                #pragma unroll
                for (int p = 0; p < 8; p++) {
                    ulonglong2 cc = row[p];
                    acc0[p] = ffma2(a00, cc.x, acc0[p]);
                    acc0[p] = ffma2(a01, cc.y, acc0[p]);
                    acc1[p] = ffma2(a10, cc.x, acc1[p]);
                    acc1[p] = ffma2(a11, cc.y, acc1[p]);
                }
            }
        }

        #pragma unroll
        for (int p = 0; p < 8; p++) {
            int base = 2 * (q * 8 + p);
            float lo, hi;
            unpk2(acc0[p], lo, hi);
            if (lo > best0) { best0 = lo; bl0 = base; }
            if (hi > best0) { best0 = hi; bl0 = base + 1; }
            unpk2(acc1[p], lo, hi);
            if (lo > best1) { best1 = lo; bl1 = base; }
            if (hi > best1) { best1 = hi; bl1 = base + 1; }
        }
    }

    g_labels[n0] = bl0;
    g_labels[n1] = bl1;
    atomicAdd(&hS[bl0], 1);
    atomicAdd(&hS[bl1], 1);
    __syncthreads();
    if (tid < NCB && hS[tid] > 0) atomicAdd(&g_hist[tid], hS[tid]);
}

// ---------------- K4: parallel scan + worklist (64 threads) ----------------
__global__ void k_scan() {
    __shared__ int cS[NCB], eS[NCB];
    int l = threadIdx.x;                 // 0..63
    int c = g_hist[l];
    int e = (c + PPB - 1) / PPB;
    cS[l] = c; eS[l] = e;
    __syncthreads();
    #pragma unroll
    for (int d = 1; d < NCB; d <<= 1) {
        int vc = (l >= d) ? cS[l - d] : 0;
        int ve = (l >= d) ? eS[l - d] : 0;
        __syncthreads();
        cS[l] += vc; eS[l] += ve;
        __syncthreads();
    }
    int excl = cS[l] - c;
    int epos = eS[l] - e;
    g_offsets[l] = excl;
    g_cursor[l] = 0;
    if (l == NCB - 1) { g_offsets[NCB] = cS[l]; g_nwork = eS[l]; }
    for (int i = 0; i < e; i++) {
        int st = i * PPB;
        g_worklist[epos + i] = make_int4(l, excl + st, min(PPB, c - st), 0);
    }
}

// ---------------- K5: scatter ----------------
__global__ void k_scatter() {
    int n = blockIdx.x * 256 + threadIdx.x;
    int lab = g_labels[n];
    int pos = atomicAdd(&g_cursor[lab], 1);
    g_perm[g_offsets[lab] + pos] = n;
}

// ---------------- K6: main PQ — 64 thr, 4 contiguous pts/thread ----------------
__global__ void __launch_bounds__(64, 4) k_main() {
    __shared__ __align__(16) u64 ckS[2][128 * DSUB];  // 2 x 16 KB
    __shared__ __align__(16) u64 cn2S[2][128];
    int bid = blockIdx.x;
    if (bid >= g_nwork) return;
    int4 w = g_worklist[bid];
    int label = w.x, start = w.y, cnt = w.z;
    int tid = threadIdx.x;

    const char* tbase = (const char*)(g_ckPair + (size_t)label * NSUB * 128 * DSUB);
    const char* cbase = (const char*)(g_cn2 + label * NSUB * 128);

    int base = 4 * tid;
    bool act = (base < cnt);                         // thread has >=1 valid point
    bool v0 = act, v1 = (base + 1 < cnt), v2 = (base + 2 < cnt), v3 = (base + 3 < cnt);
    int p0 = g_perm[start + (v0 ? base : 0)];
    int p1 = g_perm[start + (v1 ? base + 1 : 0)];
    int p2 = g_perm[start + (v2 ? base + 2 : 0)];
    int p3 = g_perm[start + (v3 ? base + 3 : 0)];
    u64 codeA = 0, codeB = 0, codeC = 0, codeD = 0;

    // prologue: async-load tile s=0 into buffer 0
    {
        char* td = (char*)ckS[0];
        #pragma unroll
        for (int i = 0; i < 16; i++)
            cpa16(td + tid * 16 + i * 1024, tbase + tid * 16 + i * 1024);
        cpa16((char*)cn2S[0] + tid * 16, cbase + tid * 16);
        cpa_commit();
    }

    for (int s = 0; s < NSUB; s++) {
        int cur = s & 1;

        float4 a0, a1, a2, a3, b0, b1, b2, b3, c0, c1, c2, c3, e0, e1, e2, e3;
        if (act) {
            const float4* xr0 = (const float4*)(g_xT + (size_t)p0 * DVEC + s * DSUB);
            const float4* xr1 = (const float4*)(g_xT + (size_t)p1 * DVEC + s * DSUB);
            const float4* xr2 = (const float4*)(g_xT + (size_t)p2 * DVEC + s * DSUB);
            const float4* xr3 = (const float4*)(g_xT + (size_t)p3 * DVEC + s * DSUB);
            a0 = xr0[0]; a1 = xr0[1]; a2 = xr0[2]; a3 = xr0[3];
            b0 = xr1[0]; b1 = xr1[1]; b2 = xr1[2]; b3 = xr1[3];
            c0 = xr2[0]; c1 = xr2[1]; c2 = xr2[2]; c3 = xr2[3];
            e0 = xr3[0]; e1 = xr3[1]; e2 = xr3[2]; e3 = xr3[3];
        }

        cpa_wait0();
        __syncthreads();

        if (s < NSUB - 1) {
            char* td = (char*)ckS[cur ^ 1];
            const char* ts = tbase + (size_t)(s + 1) * 128 * DSUB * 8;
            #pragma unroll
            for (int i = 0; i < 16; i++)
                cpa16(td + tid * 16 + i * 1024, ts + tid * 16 + i * 1024);
            cpa16((char*)cn2S[cur ^ 1] + tid * 16, cbase + (size_t)(s + 1) * 128 * 8 + tid * 16);
            cpa_commit();
        }

        if (act) {
            u64 xA[16], xB[16], xC[16], xD[16];
            xA[0]=pk2(a0.x,a0.x); xA[1]=pk2(a0.y,a0.y); xA[2]=pk2(a0.z,a0.z); xA[3]=pk2(a0.w,a0.w);
            xA[4]=pk2(a1.x,a1.x); xA[5]=pk2(a1.y,a1.y); xA[6]=pk2(a1.z,a1.z); xA[7]=pk2(a1.w,a1.w);
            xA[8]=pk2(a2.x,a2.x); xA[9]=pk2(a2.y,a2.y); xA[10]=pk2(a2.z,a2.z); xA[11]=pk2(a2.w,a2.w);
            xA[12]=pk2(a3.x,a3.x); xA[13]=pk2(a3.y,a3.y); xA[14]=pk2(a3.z,a3.z); xA[15]=pk2(a3.w,a3.w);
            xB[0]=pk2(b0.x,b0.x); xB[1]=pk2(b0.y,b0.y); xB[2]=pk2(b0.z,b0.z); xB[3]=pk2(b0.w,b0.w);
            xB[4]=pk2(b1.x,b1.x); xB[5]=pk2(b1.y,b1.y); xB[6]=pk2(b1.z,b1.z); xB[7]=pk2(b1.w,b1.w);
            xB[8]=pk2(b2.x,b2.x); xB[9]=pk2(b2.y,b2.y); xB[10]=pk2(b2.z,b2.z); xB[11]=pk2(b2.w,b2.w);
            xB[12]=pk2(b3.x,b3.x); xB[13]=pk2(b3.y,b3.y); xB[14]=pk2(b3.z,b3.z); xB[15]=pk2(b3.w,b3.w);
            xC[0]=pk2(c0.x,c0.x); xC[1]=pk2(c0.y,c0.y); xC[2]=pk2(c0.z,c0.z); xC[3]=pk2(c0.w,c0.w);
            xC[4]=pk2(c1.x,c1.x); xC[5]=pk2(c1.y,c1.y); xC[6]=pk2(c1.z,c1.z); xC[7]=pk2(c1.w,c1.w);
            xC[8]=pk2(c2.x,c2.x); xC[9]=pk2(c2.y,c2.y); xC[10]=pk2(c2.z,c2.z); xC[11]=pk2(c2.w,c2.w);
            xC[12]=pk2(c3.x,c3.x); xC[13]=pk2(c3.y,c3.y); xC[14]=pk2(c3.z,c3.z); xC[15]=pk2(c3.w,c3.w);
            xD[0]=pk2(e0.x,e0.x); xD[1]=pk2(e0.y,e0.y); xD[2]=pk2(e0.z,e0.z); xD[3]=pk2(e0.w,e0.w);
            xD[4]=pk2(e1.x,e1.x); xD[5]=pk2(e1.y,e1.y); xD[6]=pk2(e1.z,e1.z); xD[7]=pk2(e1.w,e1.w);
            xD[8]=pk2(e2.x,e2.x); xD[9]=pk2(e2.y,e2.y); xD[10]=pk2(e2.z,e2.z); xD[11]=pk2(e2.w,e2.w);
            xD[12]=pk2(e3.x,e3.x); xD[13]=pk2(e3.y,e3.y); xD[14]=pk2(e3.z,e3.z); xD[15]=pk2(e3.w,e3.w);

            float bestA = -3.4e38f, bestB = -3.4e38f, bestC = -3.4e38f, bestD = -3.4e38f;
            int kA = 0, kB = 0, kC = 0, kD = 0;

            const u64* tile = ckS[cur];
            const u64* cn2t = cn2S[cur];

            for (int p = 0; p < 128; p++) {
                const ulonglong2* cr = (const ulonglong2*)(tile + p * DSUB);
                u64 cn2 = cn2t[p];
                ulonglong2 q0 = cr[0], q1 = cr[1], q2 = cr[2], q3 = cr[3];
                u64 aA = ffma2(xA[0], q0.x, cn2);
                u64 aB = ffma2(xB[0], q0.x, cn2);
                u64 aC = ffma2(xC[0], q0.x, cn2);
                u64 aD = ffma2(xD[0], q0.x, cn2);
                aA = ffma2(xA[1], q0.y, aA);  aB = ffma2(xB[1], q0.y, aB);  aC = ffma2(xC[1], q0.y, aC);  aD = ffma2(xD[1], q0.y, aD);
                aA = ffma2(xA[2], q1.x, aA);  aB = ffma2(xB[2], q1.x, aB);  aC = ffma2(xC[2], q1.x, aC);  aD = ffma2(xD[2], q1.x, aD);
                aA = ffma2(xA[3], q1.y, aA);  aB = ffma2(xB[3], q1.y, aB);  aC = ffma2(xC[3], q1.y, aC);  aD = ffma2(xD[3], q1.y, aD);
                aA = ffma2(xA[4], q2.x, aA);  aB = ffma2(xB[4], q2.x, aB);  aC = ffma2(xC[4], q2.x, aC);  aD = ffma2(xD[4], q2.x, aD);
                aA = ffma2(xA[5], q2.y, aA);  aB = ffma2(xB[5], q2.y, aB);  aC = ffma2(xC[5], q2.y, aC);  aD = ffma2(xD[5], q2.y, aD);
                aA = ffma2(xA[6], q3.x, aA);  aB = ffma2(xB[6], q3.x, aB);  aC = ffma2(xC[6], q3.x, aC);  aD = ffma2(xD[6], q3.x, aD);
                aA = ffma2(xA[7], q3.y, aA);  aB = ffma2(xB[7], q3.y, aB);  aC = ffma2(xC[7], q3.y, aC);  aD = ffma2(xD[7], q3.y, aD);
                ulonglong2 q4 = cr[4], q5 = cr[5], q6 = cr[6], q7 = cr[7];
                aA = ffma2(xA[8],  q4.x, aA);  aB = ffma2(xB[8],  q4.x, aB);  aC = ffma2(xC[8],  q4.x, aC);  aD = ffma2(xD[8],  q4.x, aD);
                aA = ffma2(xA[9],  q4.y, aA);  aB = ffma2(xB[9],  q4.y, aB);  aC = ffma2(xC[9],  q4.y, aC);  aD = ffma2(xD[9],  q4.y, aD);
                aA = ffma2(xA[10], q5.x, aA);  aB = ffma2(xB[10], q5.x, aB);  aC = ffma2(xC[10], q5.x, aC);  aD = ffma2(xD[10], q5.x, aD);
                aA = ffma2(xA[11], q5.y, aA);  aB = ffma2(xB[11], q5.y, aB);  aC = ffma2(xC[11], q5.y, aC);  aD = ffma2(xD[11], q5.y, aD);
                aA = ffma2(xA[12], q6.x, aA);  aB = ffma2(xB[12], q6.x, aB);  aC = ffma2(xC[12], q6.x, aC);  aD = ffma2(xD[12], q6.x, aD);
                aA = ffma2(xA[13], q6.y, aA);  aB = ffma2(xB[13], q6.y, aB);  aC = ffma2(xC[13], q6.y, aC);  aD = ffma2(xD[13], q6.y, aD);
                aA = ffma2(xA[14], q7.x, aA);  aB = ffma2(xB[14], q7.x, aB);  aC = ffma2(xC[14], q7.x, aC);  aD = ffma2(xD[14], q7.x, aD);
                aA = ffma2(xA[15], q7.y, aA);  aB = ffma2(xB[15], q7.y, aB);  aC = ffma2(xC[15], q7.y, aC);  aD = ffma2(xD[15], q7.y, aD);

                float sA0, sA1, sB0, sB1, sC0, sC1, sD0, sD1;
                unpk2(aA, sA0, sA1); unpk2(aB, sB0, sB1); unpk2(aC, sC0, sC1); unpk2(aD, sD0, sD1);
                if (sA0 > bestA) { bestA = sA0; kA = 2 * p; }
                if (sA1 > bestA) { bestA = sA1; kA = 2 * p + 1; }
                if (sB0 > bestB) { bestB = sB0; kB = 2 * p; }
                if (sB1 > bestB) { bestB = sB1; kB = 2 * p + 1; }
                if (sC0 > bestC) { bestC = sC0; kC = 2 * p; }
                if (sC1 > bestC) { bestC = sC1; kC = 2 * p + 1; }
                if (sD0 > bestD) { bestD = sD0; kD = 2 * p; }
                if (sD1 > bestD) { bestD = sD1; kD = 2 * p + 1; }
            }

            codeA |= ((u64)kA) << (8 * s);
            codeB |= ((u64)kB) << (8 * s);
            codeC |= ((u64)kC) << (8 * s);
            codeD |= ((u64)kD) << (8 * s);
        }
    }
    if (v0) g_codes[p0] = codeA;
    if (v1) g_codes[p1] = codeB;
    if (v2) g_codes[p2] = codeC;
    if (v3) g_codes[p3] = codeD;
}

// ---------------- K7: decode — 4 pts/thread, STG.128 along n ----------------
__global__ void k_decode(float* __restrict__ out) {
    int t = blockIdx.x * 128 + threadIdx.x;
    int n = 4 * t;
    int lab0 = g_labels[n],     lab1 = g_labels[n + 1];
    int lab2 = g_labels[n + 2], lab3 = g_labels[n + 3];
    u64 cd0 = g_codes[n],     cd1 = g_codes[n + 1];
    u64 cd2 = g_codes[n + 2], cd3 = g_codes[n + 3];

    #pragma unroll
    for (int s = 0; s < NSUB; s++) {
        const float4* c0 = (const float4*)(g_ckPack + ((size_t)(lab0 * NSUB + s) * KCLUS + (int)((cd0 >> (8 * s)) & 255)) * DSUB);
        const float4* c1 = (const float4*)(g_ckPack + ((size_t)(lab1 * NSUB + s) * KCLUS + (int)((cd1 >> (8 * s)) & 255)) * DSUB);
        const float4* c2 = (const float4*)(g_ckPack + ((size_t)(lab2 * NSUB + s) * KCLUS + (int)((cd2 >> (8 * s)) & 255)) * DSUB);
        const float4* c3 = (const float4*)(g_ckPack + ((size_t)(lab3 * NSUB + s) * KCLUS + (int)((cd3 >> (8 * s)) & 255)) * DSUB);
        #pragma unroll
        for (int j = 0; j < 4; j++) {
            float4 v0 = c0[j], v1 = c1[j], v2 = c2[j], v3 = c3[j];
            size_t b = (size_t)(s * DSUB + 4 * j) * N_DATA + n;
            *(float4*)(out + b)              = make_float4(v0.x, v1.x, v2.x, v3.x);
            *(float4*)(out + b + N_DATA)     = make_float4(v0.y, v1.y, v2.y, v3.y);
            *(float4*)(out + b + 2 * N_DATA) = make_float4(v0.z, v1.z, v2.z, v3.z);
            *(float4*)(out + b + 3 * N_DATA) = make_float4(v0.w, v1.w, v2.w, v3.w);
        }
    }
}

// ---------------- launch ----------------
extern "C" void kernel_launch(void* const* d_in, const int* in_sizes, int n_in,
                              void* d_out, int out_size) {
    const float* x   = (const float*)d_in[0];
    const float* cb  = (const float*)d_in[1];
    const float* sel = (const float*)d_in[2];
    float* out = (float*)d_out;

    k_pack<<<NCB * NSUB + 1, 256>>>(cb, sel);
    k_label<<<N_DATA / 512, 256>>>(x);
    k_scan<<<1, 64>>>();
    k_scatter<<<N_DATA / 256, 256>>>();
    k_main<<<MAXWORK, 64>>>();
    k_decode<<<N_DATA / 512, 128>>>(out);
}

// round 9
// speedup vs baseline: 1.1304x; 1.1304x over previous
#include <cuda_runtime.h>
#include <cstdint>

#define N_DATA 131072
#define DVEC   128
#define NSUB   8
#define DSUB   16
#define KCLUS  256
#define NCB    64
#define PPB    256
#define MAXWORK 640            // worst case 512 + 64 partials = 576

typedef unsigned long long u64;

// ---------------- device scratch ----------------
__device__ float g_xT[(size_t)N_DATA * DVEC];                       // 67 MB x transposed [n][d]
__device__ float g_ckPack[NCB * NSUB * KCLUS * DSUB];               // 8 MB [cb][s][k][d] (decode)
__device__ __align__(16) u64 g_ckPair[(size_t)NCB * NSUB * 128 * DSUB]; // 8 MB pair-packed
__device__ __align__(16) u64 g_cn2[NCB * NSUB * 128];               // (-cn(2p)/2, -cn(2p+1)/2)
__device__ __align__(16) u64 g_selPair[64 * 32 * 2];                // [dstep][pair][2dims]
__device__ u64   g_ln2[32];
__device__ int   g_lp[N_DATA];        // (posInLabel<<6) | label
__device__ int   g_perm[N_DATA];
__device__ u64   g_codes[N_DATA];
__device__ int   g_hist[NCB];
__device__ int   g_offsets[NCB + 1];
__device__ int4  g_worklist[MAXWORK];
__device__ int   g_nwork;

// ---------------- helpers ----------------
__device__ __forceinline__ u64 pk2(float lo, float hi) {
    u64 r; asm("mov.b64 %0, {%1,%2};" : "=l"(r) : "f"(lo), "f"(hi)); return r;
}
__device__ __forceinline__ void unpk2(u64 v, float& lo, float& hi) {
    asm("mov.b64 {%0,%1}, %2;" : "=f"(lo), "=f"(hi) : "l"(v));
}
__device__ __forceinline__ u64 ffma2(u64 a, u64 b, u64 c) {
    u64 d; asm("fma.rn.f32x2 %0, %1, %2, %3;" : "=l"(d) : "l"(a), "l"(b), "l"(c)); return d;
}
__device__ __forceinline__ void cpa16(void* dst, const void* src) {
    unsigned int d = (unsigned int)__cvta_generic_to_shared(dst);
    asm volatile("cp.async.cg.shared.global [%0], [%1], 16;" :: "r"(d), "l"(src));
}
__device__ __forceinline__ void cpa_commit() { asm volatile("cp.async.commit_group;"); }
__device__ __forceinline__ void cpa_wait0()  { asm volatile("cp.async.wait_group 0;"); }

// ---------------- K1: pack codebook + selector (+ zero hist) ----------------
__global__ void k_pack(const float* __restrict__ cb, const float* __restrict__ sel) {
    int bid = blockIdx.x, tid = threadIdx.x;
    if (bid < NCB * NSUB) {
        __shared__ float t[DSUB][KCLUS + 1];
        __shared__ float cnsh[KCLUS];
        const float* src = cb + (size_t)bid * DSUB * KCLUS;
        for (int i = tid; i < DSUB * KCLUS; i += 256) t[i >> 8][i & 255] = src[i];
        __syncthreads();
        int k = tid;
        float v[DSUB]; float cn = 0.f;
        #pragma unroll
        for (int d = 0; d < DSUB; d++) { v[d] = t[d][k]; cn = fmaf(v[d], v[d], cn); }
        float4* dst = (float4*)(g_ckPack + ((size_t)bid * KCLUS + k) * DSUB);
        dst[0] = make_float4(v[0], v[1], v[2], v[3]);
        dst[1] = make_float4(v[4], v[5], v[6], v[7]);
        dst[2] = make_float4(v[8], v[9], v[10], v[11]);
        dst[3] = make_float4(v[12], v[13], v[14], v[15]);
        cnsh[k] = cn;
        __syncthreads();
        if (tid < 128) {
            int p = tid;
            g_cn2[bid * 128 + p] = pk2(-0.5f * cnsh[2 * p], -0.5f * cnsh[2 * p + 1]);
            u64* dp = g_ckPair + ((size_t)bid * 128 + p) * DSUB;
            #pragma unroll
            for (int d = 0; d < DSUB; d++)
                dp[d] = pk2(t[d][2 * p], t[d][2 * p + 1]);
        }
    } else {
        __shared__ float cnselS[NCB];
        if (tid < NCB) {
            g_hist[tid] = 0;                                  // fused k_init
            float s = 0.f;
            for (int d = 0; d < DVEC; d++) { float v = sel[d * NCB + tid]; s = fmaf(v, v, s); }
            cnselS[tid] = s;
        }
        __syncthreads();
        if (tid < 32) g_ln2[tid] = pk2(-0.5f * cnselS[2 * tid], -0.5f * cnselS[2 * tid + 1]);
        for (int i = tid; i < 64 * 32 * 2; i += 256) {
            int ds = i >> 6, r = i & 63, p = r >> 1, j = r & 1, d = 2 * ds + j;
            g_selPair[i] = pk2(sel[d * NCB + 2 * p], sel[d * NCB + 2 * p + 1]);
        }
    }
}

// ---------------- K3: labels + fused xT write + rank assignment ----------------
__global__ void __launch_bounds__(256, 2) k_label(const float* __restrict__ x) {
    __shared__ __align__(16) u64 selS[64 * 32 * 2];  // 32 KB
    __shared__ u64 ln2S[32];
    __shared__ int hS[NCB];      // running per-block rank counters -> final counts
    __shared__ int baseS[NCB];   // block's base within each label's global region
    int tid = threadIdx.x;
    for (int i = tid; i < 2048; i += 256)
        ((ulonglong2*)selS)[i] = ((const ulonglong2*)g_selPair)[i];
    if (tid < 32) ln2S[tid] = g_ln2[tid];
    if (tid < NCB) hS[tid] = 0;
    __syncthreads();

    int n0 = blockIdx.x * 512 + tid;
    int n1 = n0 + 256;
    const float* xc0 = x + n0;
    const float* xc1 = x + n1;

    float best0 = -3.4e38f, best1 = -3.4e38f;
    int bl0 = 0, bl1 = 0;

    for (int q = 0; q < 4; q++) {
        u64 acc0[8], acc1[8];
        #pragma unroll
        for (int p = 0; p < 8; p++) { u64 v = ln2S[q * 8 + p]; acc0[p] = v; acc1[p] = v; }

        for (int c = 0; c < 16; c++) {
            float xr0[8], xr1[8];
            const float* xp0 = xc0 + (size_t)(8 * c) * N_DATA;
            const float* xp1 = xc1 + (size_t)(8 * c) * N_DATA;
            #pragma unroll
            for (int i = 0; i < 8; i++) xr0[i] = xp0[(size_t)i * N_DATA];
            #pragma unroll
            for (int i = 0; i < 8; i++) xr1[i] = xp1[(size_t)i * N_DATA];

            if (q == 0) {
                float4* d0 = (float4*)(g_xT + (size_t)n0 * DVEC + 8 * c);
                float4* d1 = (float4*)(g_xT + (size_t)n1 * DVEC + 8 * c);
                d0[0] = make_float4(xr0[0], xr0[1], xr0[2], xr0[3]);
                d0[1] = make_float4(xr0[4], xr0[5], xr0[6], xr0[7]);
                d1[0] = make_float4(xr1[0], xr1[1], xr1[2], xr1[3]);
                d1[1] = make_float4(xr1[4], xr1[5], xr1[6], xr1[7]);
            }

            #pragma unroll
            for (int i2 = 0; i2 < 4; i2++) {
                int ds = 4 * c + i2;
                u64 a00 = pk2(xr0[2 * i2], xr0[2 * i2]);
                u64 a01 = pk2(xr0[2 * i2 + 1], xr0[2 * i2 + 1]);
                u64 a10 = pk2(xr1[2 * i2], xr1[2 * i2]);
                u64 a11 = pk2(xr1[2 * i2 + 1], xr1[2 * i2 + 1]);
                const ulonglong2* row = (const ulonglong2*)(selS + ds * 64 + q * 16);
                #pragma unroll
                for (int p = 0; p < 8; p++) {
                    ulonglong2 cc = row[p];
                    acc0[p] = ffma2(a00, cc.x, acc0[p]);
                    acc0[p] = ffma2(a01, cc.y, acc0[p]);
                    acc1[p] = ffma2(a10, cc.x, acc1[p]);
                    acc1[p] = ffma2(a11, cc.y, acc1[p]);
                }
            }
        }

        #pragma unroll
        for (int p = 0; p < 8; p++) {
            int base = 2 * (q * 8 + p);
            float lo, hi;
            unpk2(acc0[p], lo, hi);
            if (lo > best0) { best0 = lo; bl0 = base; }
            if (hi > best0) { best0 = hi; bl0 = base + 1; }
            unpk2(acc1[p], lo, hi);
            if (lo > best1) { best1 = lo; bl1 = base; }
            if (hi > best1) { best1 = hi; bl1 = base + 1; }
        }
    }

    // per-block rank, then one global atomic per (block,label) reserves the range
    int r0 = atomicAdd(&hS[bl0], 1);
    int r1 = atomicAdd(&hS[bl1], 1);
    __syncthreads();
    if (tid < NCB) {
        int c = hS[tid];
        baseS[tid] = (c > 0) ? atomicAdd(&g_hist[tid], c) : 0;
    }
    __syncthreads();
    g_lp[n0] = ((baseS[bl0] + r0) << 6) | bl0;
    g_lp[n1] = ((baseS[bl1] + r1) << 6) | bl1;
}

// ---------------- K4: parallel scan + worklist (64 threads) ----------------
__global__ void k_scan() {
    __shared__ int cS[NCB], eS[NCB];
    int l = threadIdx.x;                 // 0..63
    int c = g_hist[l];
    int e = (c + PPB - 1) / PPB;
    cS[l] = c; eS[l] = e;
    __syncthreads();
    #pragma unroll
    for (int d = 1; d < NCB; d <<= 1) {
        int vc = (l >= d) ? cS[l - d] : 0;
        int ve = (l >= d) ? eS[l - d] : 0;
        __syncthreads();
        cS[l] += vc; eS[l] += ve;
        __syncthreads();
    }
    int excl = cS[l] - c;
    int epos = eS[l] - e;
    g_offsets[l] = excl;
    if (l == NCB - 1) { g_offsets[NCB] = cS[l]; g_nwork = eS[l]; }
    for (int i = 0; i < e; i++) {
        int st = i * PPB;
        g_worklist[epos + i] = make_int4(l, excl + st, min(PPB, c - st), 0);
    }
}

// ---------------- K5: scatter — NO atomics ----------------
__global__ void k_scatter() {
    __shared__ int offS[NCB];
    int tid = threadIdx.x;
    if (tid < NCB) offS[tid] = g_offsets[tid];
    __syncthreads();
    int n = blockIdx.x * 256 + tid;
    int lp = g_lp[n];
    g_perm[offS[lp & 63] + (lp >> 6)] = n;
}

// ---------------- K6: main PQ — 64 thr, 4 contiguous pts/thread ----------------
__global__ void __launch_bounds__(64, 4) k_main() {
    __shared__ __align__(16) u64 ckS[2][128 * DSUB];  // 2 x 16 KB
    __shared__ __align__(16) u64 cn2S[2][128];
    int bid = blockIdx.x;
    if (bid >= g_nwork) return;
    int4 w = g_worklist[bid];
    int label = w.x, start = w.y, cnt = w.z;
    int tid = threadIdx.x;

    const char* tbase = (const char*)(g_ckPair + (size_t)label * NSUB * 128 * DSUB);
    const char* cbase = (const char*)(g_cn2 + label * NSUB * 128);

    int base = 4 * tid;
    bool act = (base < cnt);
    bool v0 = act, v1 = (base + 1 < cnt), v2 = (base + 2 < cnt), v3 = (base + 3 < cnt);
    int p0 = g_perm[start + (v0 ? base : 0)];
    int p1 = g_perm[start + (v1 ? base + 1 : 0)];
    int p2 = g_perm[start + (v2 ? base + 2 : 0)];
    int p3 = g_perm[start + (v3 ? base + 3 : 0)];
    u64 codeA = 0, codeB = 0, codeC = 0, codeD = 0;

    {
        char* td = (char*)ckS[0];
        #pragma unroll
        for (int i = 0; i < 16; i++)
            cpa16(td + tid * 16 + i * 1024, tbase + tid * 16 + i * 1024);
        cpa16((char*)cn2S[0] + tid * 16, cbase + tid * 16);
        cpa_commit();
    }

    for (int s = 0; s < NSUB; s++) {
        int cur = s & 1;

        float4 a0, a1, a2, a3, b0, b1, b2, b3, c0, c1, c2, c3, e0, e1, e2, e3;
        if (act) {
            const float4* xr0 = (const float4*)(g_xT + (size_t)p0 * DVEC + s * DSUB);
            const float4* xr1 = (const float4*)(g_xT + (size_t)p1 * DVEC + s * DSUB);
            const float4* xr2 = (const float4*)(g_xT + (size_t)p2 * DVEC + s * DSUB);
            const float4* xr3 = (const float4*)(g_xT + (size_t)p3 * DVEC + s * DSUB);
            a0 = xr0[0]; a1 = xr0[1]; a2 = xr0[2]; a3 = xr0[3];
            b0 = xr1[0]; b1 = xr1[1]; b2 = xr1[2]; b3 = xr1[3];
            c0 = xr2[0]; c1 = xr2[1]; c2 = xr2[2]; c3 = xr2[3];
            e0 = xr3[0]; e1 = xr3[1]; e2 = xr3[2]; e3 = xr3[3];
        }

        cpa_wait0();
        __syncthreads();

        if (s < NSUB - 1) {
            char* td = (char*)ckS[cur ^ 1];
            const char* ts = tbase + (size_t)(s + 1) * 128 * DSUB * 8;
            #pragma unroll
            for (int i = 0; i < 16; i++)
                cpa16(td + tid * 16 + i * 1024, ts + tid * 16 + i * 1024);
            cpa16((char*)cn2S[cur ^ 1] + tid * 16, cbase + (size_t)(s + 1) * 128 * 8 + tid * 16);
            cpa_commit();
        }

        if (act) {
            u64 xA[16], xB[16], xC[16], xD[16];
            xA[0]=pk2(a0.x,a0.x); xA[1]=pk2(a0.y,a0.y); xA[2]=pk2(a0.z,a0.z); xA[3]=pk2(a0.w,a0.w);
            xA[4]=pk2(a1.x,a1.x); xA[5]=pk2(a1.y,a1.y); xA[6]=pk2(a1.z,a1.z); xA[7]=pk2(a1.w,a1.w);
            xA[8]=pk2(a2.x,a2.x); xA[9]=pk2(a2.y,a2.y); xA[10]=pk2(a2.z,a2.z); xA[11]=pk2(a2.w,a2.w);
            xA[12]=pk2(a3.x,a3.x); xA[13]=pk2(a3.y,a3.y); xA[14]=pk2(a3.z,a3.z); xA[15]=pk2(a3.w,a3.w);
            xB[0]=pk2(b0.x,b0.x); xB[1]=pk2(b0.y,b0.y); xB[2]=pk2(b0.z,b0.z); xB[3]=pk2(b0.w,b0.w);
            xB[4]=pk2(b1.x,b1.x); xB[5]=pk2(b1.y,b1.y); xB[6]=pk2(b1.z,b1.z); xB[7]=pk2(b1.w,b1.w);
            xB[8]=pk2(b2.x,b2.x); xB[9]=pk2(b2.y,b2.y); xB[10]=pk2(b2.z,b2.z); xB[11]=pk2(b2.w,b2.w);
            xB[12]=pk2(b3.x,b3.x); xB[13]=pk2(b3.y,b3.y); xB[14]=pk2(b3.z,b3.z); xB[15]=pk2(b3.w,b3.w);
            xC[0]=pk2(c0.x,c0.x); xC[1]=pk2(c0.y,c0.y); xC[2]=pk2(c0.z,c0.z); xC[3]=pk2(c0.w,c0.w);
            xC[4]=pk2(c1.x,c1.x); xC[5]=pk2(c1.y,c1.y); xC[6]=pk2(c1.z,c1.z); xC[7]=pk2(c1.w,c1.w);
            xC[8]=pk2(c2.x,c2.x); xC[9]=pk2(c2.y,c2.y); xC[10]=pk2(c2.z,c2.z); xC[11]=pk2(c2.w,c2.w);
            xC[12]=pk2(c3.x,c3.x); xC[13]=pk2(c3.y,c3.y); xC[14]=pk2(c3.z,c3.z); xC[15]=pk2(c3.w,c3.w);
            xD[0]=pk2(e0.x,e0.x); xD[1]=pk2(e0.y,e0.y); xD[2]=pk2(e0.z,e0.z); xD[3]=pk2(e0.w,e0.w);
            xD[4]=pk2(e1.x,e1.x); xD[5]=pk2(e1.y,e1.y); xD[6]=pk2(e1.z,e1.z); xD[7]=pk2(e1.w,e1.w);
            xD[8]=pk2(e2.x,e2.x); xD[9]=pk2(e2.y,e2.y); xD[10]=pk2(e2.z,e2.z); xD[11]=pk2(e2.w,e2.w);
            xD[12]=pk2(e3.x,e3.x); xD[13]=pk2(e3.y,e3.y); xD[14]=pk2(e3.z,e3.z); xD[15]=pk2(e3.w,e3.w);

            float bestA = -3.4e38f, bestB = -3.4e38f, bestC = -3.4e38f, bestD = -3.4e38f;
            int kA = 0, kB = 0, kC = 0, kD = 0;

            const u64* tile = ckS[cur];
            const u64* cn2t = cn2S[cur];

            for (int p = 0; p < 128; p++) {
                const ulonglong2* cr = (const ulonglong2*)(tile + p * DSUB);
                u64 cn2 = cn2t[p];
                ulonglong2 q0 = cr[0], q1 = cr[1], q2 = cr[2], q3 = cr[3];
                u64 aA = ffma2(xA[0], q0.x, cn2);
                u64 aB = ffma2(xB[0], q0.x, cn2);
                u64 aC = ffma2(xC[0], q0.x, cn2);
                u64 aD = ffma2(xD[0], q0.x, cn2);
                aA = ffma2(xA[1], q0.y, aA);  aB = ffma2(xB[1], q0.y, aB);  aC = ffma2(xC[1], q0.y, aC);  aD = ffma2(xD[1], q0.y, aD);
                aA = ffma2(xA[2], q1.x, aA);  aB = ffma2(xB[2], q1.x, aB);  aC = ffma2(xC[2], q1.x, aC);  aD = ffma2(xD[2], q1.x, aD);
                aA = ffma2(xA[3], q1.y, aA);  aB = ffma2(xB[3], q1.y, aB);  aC = ffma2(xC[3], q1.y, aC);  aD = ffma2(xD[3], q1.y, aD);
                aA = ffma2(xA[4], q2.x, aA);  aB = ffma2(xB[4], q2.x, aB);  aC = ffma2(xC[4], q2.x, aC);  aD = ffma2(xD[4], q2.x, aD);
                aA = ffma2(xA[5], q2.y, aA);  aB = ffma2(xB[5], q2.y, aB);  aC = ffma2(xC[5], q2.y, aC);  aD = ffma2(xD[5], q2.y, aD);
                aA = ffma2(xA[6], q3.x, aA);  aB = ffma2(xB[6], q3.x, aB);  aC = ffma2(xC[6], q3.x, aC);  aD = ffma2(xD[6], q3.x, aD);
                aA = ffma2(xA[7], q3.y, aA);  aB = ffma2(xB[7], q3.y, aB);  aC = ffma2(xC[7], q3.y, aC);  aD = ffma2(xD[7], q3.y, aD);
                ulonglong2 q4 = cr[4], q5 = cr[5], q6 = cr[6], q7 = cr[7];
                aA = ffma2(xA[8],  q4.x, aA);  aB = ffma2(xB[8],  q4.x, aB);  aC = ffma2(xC[8],  q4.x, aC);  aD = ffma2(xD[8],  q4.x, aD);
                aA = ffma2(xA[9],  q4.y, aA);  aB = ffma2(xB[9],  q4.y, aB);  aC = ffma2(xC[9],  q4.y, aC);  aD = ffma2(xD[9],  q4.y, aD);
                aA = ffma2(xA[10], q5.x, aA);  aB = ffma2(xB[10], q5.x, aB);  aC = ffma2(xC[10], q5.x, aC);  aD = ffma2(xD[10], q5.x, aD);
                aA = ffma2(xA[11], q5.y, aA);  aB = ffma2(xB[11], q5.y, aB);  aC = ffma2(xC[11], q5.y, aC);  aD = ffma2(xD[11], q5.y, aD);
                aA = ffma2(xA[12], q6.x, aA);  aB = ffma2(xB[12], q6.x, aB);  aC = ffma2(xC[12], q6.x, aC);  aD = ffma2(xD[12], q6.x, aD);
                aA = ffma2(xA[13], q6.y, aA);  aB = ffma2(xB[13], q6.y, aB);  aC = ffma2(xC[13], q6.y, aC);  aD = ffma2(xD[13], q6.y, aD);
                aA = ffma2(xA[14], q7.x, aA);  aB = ffma2(xB[14], q7.x, aB);  aC = ffma2(xC[14], q7.x, aC);  aD = ffma2(xD[14], q7.x, aD);
                aA = ffma2(xA[15], q7.y, aA);  aB = ffma2(xB[15], q7.y, aB);  aC = ffma2(xC[15], q7.y, aC);  aD = ffma2(xD[15], q7.y, aD);

                float sA0, sA1, sB0, sB1, sC0, sC1, sD0, sD1;
                unpk2(aA, sA0, sA1); unpk2(aB, sB0, sB1); unpk2(aC, sC0, sC1); unpk2(aD, sD0, sD1);
                if (sA0 > bestA) { bestA = sA0; kA = 2 * p; }
                if (sA1 > bestA) { bestA = sA1; kA = 2 * p + 1; }
                if (sB0 > bestB) { bestB = sB0; kB = 2 * p; }
                if (sB1 > bestB) { bestB = sB1; kB = 2 * p + 1; }
                if (sC0 > bestC) { bestC = sC0; kC = 2 * p; }
                if (sC1 > bestC) { bestC = sC1; kC = 2 * p + 1; }
                if (sD0 > bestD) { bestD = sD0; kD = 2 * p; }
                if (sD1 > bestD) { bestD = sD1; kD = 2 * p + 1; }
            }

            codeA |= ((u64)kA) << (8 * s);
            codeB |= ((u64)kB) << (8 * s);
            codeC |= ((u64)kC) << (8 * s);
            codeD |= ((u64)kD) << (8 * s);
        }
    }
    if (v0) g_codes[p0] = codeA;
    if (v1) g_codes[p1] = codeB;
    if (v2) g_codes[p2] = codeC;
    if (v3) g_codes[p3] = codeD;
}

// ---------------- K7: decode — 4 pts/thread, STG.128 along n ----------------
__global__ void k_decode(float* __restrict__ out) {
    int t = blockIdx.x * 128 + threadIdx.x;
    int n = 4 * t;
    int lab0 = g_lp[n] & 63,     lab1 = g_lp[n + 1] & 63;
    int lab2 = g_lp[n + 2] & 63, lab3 = g_lp[n + 3] & 63;
    u64 cd0 = g_codes[n],     cd1 = g_codes[n + 1];
    u64 cd2 = g_codes[n + 2], cd3 = g_codes[n + 3];

    #pragma unroll
    for (int s = 0; s < NSUB; s++) {
        const float4* c0 = (const float4*)(g_ckPack + ((size_t)(lab0 * NSUB + s) * KCLUS + (int)((cd0 >> (8 * s)) & 255)) * DSUB);
        const float4* c1 = (const float4*)(g_ckPack + ((size_t)(lab1 * NSUB + s) * KCLUS + (int)((cd1 >> (8 * s)) & 255)) * DSUB);
        const float4* c2 = (const float4*)(g_ckPack + ((size_t)(lab2 * NSUB + s) * KCLUS + (int)((cd2 >> (8 * s)) & 255)) * DSUB);
        const float4* c3 = (const float4*)(g_ckPack + ((size_t)(lab3 * NSUB + s) * KCLUS + (int)((cd3 >> (8 * s)) & 255)) * DSUB);
        #pragma unroll
        for (int j = 0; j < 4; j++) {
            float4 v0 = c0[j], v1 = c1[j], v2 = c2[j], v3 = c3[j];
            size_t b = (size_t)(s * DSUB + 4 * j) * N_DATA + n;
            *(float4*)(out + b)              = make_float4(v0.x, v1.x, v2.x, v3.x);
            *(float4*)(out + b + N_DATA)     = make_float4(v0.y, v1.y, v2.y, v3.y);
            *(float4*)(out + b + 2 * N_DATA) = make_float4(v0.z, v1.z, v2.z, v3.z);
            *(float4*)(out + b + 3 * N_DATA) = make_float4(v0.w, v1.w, v2.w, v3.w);
        }
    }
}

// ---------------- launch ----------------
extern "C" void kernel_launch(void* const* d_in, const int* in_sizes, int n_in,
                              void* d_out, int out_size) {
    const float* x   = (const float*)d_in[0];
    const float* cb  = (const float*)d_in[1];
    const float* sel = (const float*)d_in[2];
    float* out = (float*)d_out;

    k_pack<<<NCB * NSUB + 1, 256>>>(cb, sel);
    k_label<<<N_DATA / 512, 256>>>(x);
    k_scan<<<1, 64>>>();
    k_scatter<<<N_DATA / 256, 256>>>();
    k_main<<<MAXWORK, 64>>>();
    k_decode<<<N_DATA / 512, 128>>>(out);
}

// round 10
// speedup vs baseline: 1.1595x; 1.0257x over previous
#include <cuda_runtime.h>
#include <cstdint>

#define N_DATA 131072
#define DVEC   128
#define NSUB   8
#define DSUB   16
#define KCLUS  256
#define NCB    64
#define PPB    256
#define MAXWORK 640            // worst case 512 + 64 partials = 576
#define NLABBLK 256            // label blocks in fused kernel

typedef unsigned long long u64;

// ---------------- device scratch ----------------
__device__ float g_xT[(size_t)N_DATA * DVEC];                       // 67 MB x transposed [n][d]
__device__ float g_ckPack[NCB * NSUB * KCLUS * DSUB];               // 8 MB [cb][s][k][d] (decode)
__device__ __align__(16) u64 g_ckPair[(size_t)NCB * NSUB * 128 * DSUB]; // 8 MB pair-packed
__device__ __align__(16) u64 g_cn2[NCB * NSUB * 128];               // (-cn(2p)/2, -cn(2p+1)/2)
__device__ __align__(16) u64 g_selPair[64 * 32 * 2];                // [dstep][pair][2dims]
__device__ u64   g_ln2[32];
__device__ int   g_lp[N_DATA];        // (posInLabel<<6) | label
__device__ int   g_perm[N_DATA];
__device__ u64   g_codes[N_DATA];
__device__ int   g_hist[NCB];
__device__ int   g_offsets[NCB + 1];
__device__ int4  g_worklist[MAXWORK];
__device__ int   g_nwork;
__device__ int   g_done;

// ---------------- helpers ----------------
__device__ __forceinline__ u64 pk2(float lo, float hi) {
    u64 r; asm("mov.b64 %0, {%1,%2};" : "=l"(r) : "f"(lo), "f"(hi)); return r;
}
__device__ __forceinline__ void unpk2(u64 v, float& lo, float& hi) {
    asm("mov.b64 {%0,%1}, %2;" : "=f"(lo), "=f"(hi) : "l"(v));
}
__device__ __forceinline__ u64 ffma2(u64 a, u64 b, u64 c) {
    u64 d; asm("fma.rn.f32x2 %0, %1, %2, %3;" : "=l"(d) : "l"(a), "l"(b), "l"(c)); return d;
}
__device__ __forceinline__ void cpa16(void* dst, const void* src) {
    unsigned int d = (unsigned int)__cvta_generic_to_shared(dst);
    asm volatile("cp.async.cg.shared.global [%0], [%1], 16;" :: "r"(d), "l"(src));
}
__device__ __forceinline__ void cpa_commit() { asm volatile("cp.async.commit_group;"); }
__device__ __forceinline__ void cpa_wait0()  { asm volatile("cp.async.wait_group 0;"); }

// ---------------- K0: selector pack + state zero (tiny) ----------------
__global__ void k_selpack(const float* __restrict__ sel) {
    __shared__ float cnselS[NCB];
    int tid = threadIdx.x;
    if (tid < NCB) {
        g_hist[tid] = 0;
        float s = 0.f;
        for (int d = 0; d < DVEC; d++) { float v = sel[d * NCB + tid]; s = fmaf(v, v, s); }
        cnselS[tid] = s;
    }
    if (tid == 0) g_done = 0;
    __syncthreads();
    if (tid < 32) g_ln2[tid] = pk2(-0.5f * cnselS[2 * tid], -0.5f * cnselS[2 * tid + 1]);
    for (int i = tid; i < 64 * 32 * 2; i += 256) {
        int ds = i >> 6, r = i & 63, p = r >> 1, j = r & 1, d = 2 * ds + j;
        g_selPair[i] = pk2(sel[d * NCB + 2 * p], sel[d * NCB + 2 * p + 1]);
    }
}

// ---------------- K1: fused labels + xT + rank + codebook pack + scan ----------------
__global__ void __launch_bounds__(256, 2) k_labelpack(const float* __restrict__ x,
                                                      const float* __restrict__ cb) {
    __shared__ union {
        struct { u64 selS[64 * 32 * 2]; u64 ln2S[32]; int hS[NCB]; int baseS[NCB]; } lab;
        struct { float t[DSUB][KCLUS + 1]; float cnsh[KCLUS]; } pk;
        struct { int cS[NCB]; int eS[NCB]; } sc;
    } sm;
    __shared__ int isLast;
    int tid = threadIdx.x;
    int bid = blockIdx.x;

    if (bid >= NLABBLK) {
        // ------- codebook pack block -------
        int pb = bid - NLABBLK;                   // 0..511 = cb*NSUB+s
        const float* src = cb + (size_t)pb * DSUB * KCLUS;
        for (int i = tid; i < DSUB * KCLUS; i += 256) sm.pk.t[i >> 8][i & 255] = src[i];
        __syncthreads();
        int k = tid;
        float v[DSUB]; float cn = 0.f;
        #pragma unroll
        for (int d = 0; d < DSUB; d++) { v[d] = sm.pk.t[d][k]; cn = fmaf(v[d], v[d], cn); }
        float4* dst = (float4*)(g_ckPack + ((size_t)pb * KCLUS + k) * DSUB);
        dst[0] = make_float4(v[0], v[1], v[2], v[3]);
        dst[1] = make_float4(v[4], v[5], v[6], v[7]);
        dst[2] = make_float4(v[8], v[9], v[10], v[11]);
        dst[3] = make_float4(v[12], v[13], v[14], v[15]);
        sm.pk.cnsh[k] = cn;
        __syncthreads();
        if (tid < 128) {
            int p = tid;
            g_cn2[pb * 128 + p] = pk2(-0.5f * sm.pk.cnsh[2 * p], -0.5f * sm.pk.cnsh[2 * p + 1]);
            u64* dp = g_ckPair + ((size_t)pb * 128 + p) * DSUB;
            #pragma unroll
            for (int d = 0; d < DSUB; d++)
                dp[d] = pk2(sm.pk.t[d][2 * p], sm.pk.t[d][2 * p + 1]);
        }
        return;
    }

    // ------- label block -------
    for (int i = tid; i < 2048; i += 256)
        ((ulonglong2*)sm.lab.selS)[i] = ((const ulonglong2*)g_selPair)[i];
    if (tid < 32) sm.lab.ln2S[tid] = g_ln2[tid];
    if (tid < NCB) sm.lab.hS[tid] = 0;
    __syncthreads();

    int n0 = bid * 512 + tid;
    int n1 = n0 + 256;
    const float* xc0 = x + n0;
    const float* xc1 = x + n1;

    float best0 = -3.4e38f, best1 = -3.4e38f;
    int bl0 = 0, bl1 = 0;

    for (int q = 0; q < 4; q++) {
        u64 acc0[8], acc1[8];
        #pragma unroll
        for (int p = 0; p < 8; p++) { u64 v = sm.lab.ln2S[q * 8 + p]; acc0[p] = v; acc1[p] = v; }

        float xr0[8], xr1[8];
        #pragma unroll
        for (int i = 0; i < 8; i++) xr0[i] = xc0[(size_t)i * N_DATA];
        #pragma unroll
        for (int i = 0; i < 8; i++) xr1[i] = xc1[(size_t)i * N_DATA];

        for (int c = 0; c < 16; c++) {
            float xn0[8], xn1[8];
            if (c < 15) {
                const float* xp0 = xc0 + (size_t)(8 * (c + 1)) * N_DATA;
                const float* xp1 = xc1 + (size_t)(8 * (c + 1)) * N_DATA;
                #pragma unroll
                for (int i = 0; i < 8; i++) xn0[i] = xp0[(size_t)i * N_DATA];
                #pragma unroll
                for (int i = 0; i < 8; i++) xn1[i] = xp1[(size_t)i * N_DATA];
            }

            if (q == 0) {
                float4* d0 = (float4*)(g_xT + (size_t)n0 * DVEC + 8 * c);
                float4* d1 = (float4*)(g_xT + (size_t)n1 * DVEC + 8 * c);
                d0[0] = make_float4(xr0[0], xr0[1], xr0[2], xr0[3]);
                d0[1] = make_float4(xr0[4], xr0[5], xr0[6], xr0[7]);
                d1[0] = make_float4(xr1[0], xr1[1], xr1[2], xr1[3]);
                d1[1] = make_float4(xr1[4], xr1[5], xr1[6], xr1[7]);
            }

            #pragma unroll
            for (int i2 = 0; i2 < 4; i2++) {
                int ds = 4 * c + i2;
                u64 a00 = pk2(xr0[2 * i2], xr0[2 * i2]);
                u64 a01 = pk2(xr0[2 * i2 + 1], xr0[2 * i2 + 1]);
                u64 a10 = pk2(xr1[2 * i2], xr1[2 * i2]);
                u64 a11 = pk2(xr1[2 * i2 + 1], xr1[2 * i2 + 1]);
                const ulonglong2* row = (const ulonglong2*)(sm.lab.selS + ds * 64 + q * 16);
                #pragma unroll
                for (int p = 0; p < 8; p++) {
                    ulonglong2 cc = row[p];
                    acc0[p] = ffma2(a00, cc.x, acc0[p]);
                    acc0[p] = ffma2(a01, cc.y, acc0[p]);
                    acc1[p] = ffma2(a10, cc.x, acc1[p]);
                    acc1[p] = ffma2(a11, cc.y, acc1[p]);
                }
            }
            #pragma unroll
            for (int i = 0; i < 8; i++) { xr0[i] = xn0[i]; xr1[i] = xn1[i]; }
        }

        #pragma unroll
        for (int p = 0; p < 8; p++) {
            int base = 2 * (q * 8 + p);
            float lo, hi;
            unpk2(acc0[p], lo, hi);
            if (lo > best0) { best0 = lo; bl0 = base; }
            if (hi > best0) { best0 = hi; bl0 = base + 1; }
            unpk2(acc1[p], lo, hi);
            if (lo > best1) { best1 = lo; bl1 = base; }
            if (hi > best1) { best1 = hi; bl1 = base + 1; }
        }
    }

    // rank within block, then one global atomic per (block,label)
    int r0 = atomicAdd(&sm.lab.hS[bl0], 1);
    int r1 = atomicAdd(&sm.lab.hS[bl1], 1);
    __syncthreads();
    if (tid < NCB) {
        int c = sm.lab.hS[tid];
        sm.lab.baseS[tid] = (c > 0) ? atomicAdd(&g_hist[tid], c) : 0;
    }
    __syncthreads();
    g_lp[n0] = ((sm.lab.baseS[bl0] + r0) << 6) | bl0;
    g_lp[n1] = ((sm.lab.baseS[bl1] + r1) << 6) | bl1;

    // ------- fused scan: last label block to finish builds offsets + worklist -------
    if (tid == 0) {
        __threadfence();
        int old = atomicAdd(&g_done, 1);
        isLast = (old == NLABBLK - 1);
    }
    __syncthreads();
    if (isLast) {
        int l = tid;
        int c = 0, e = 0;
        if (l < NCB) {
            c = g_hist[l];
            e = (c + PPB - 1) / PPB;
            sm.sc.cS[l] = c; sm.sc.eS[l] = e;
        }
        __syncthreads();
        #pragma unroll
        for (int d = 1; d < NCB; d <<= 1) {
            int vc = 0, ve = 0;
            if (l < NCB && l >= d) { vc = sm.sc.cS[l - d]; ve = sm.sc.eS[l - d]; }
            __syncthreads();
            if (l < NCB) { sm.sc.cS[l] += vc; sm.sc.eS[l] += ve; }
            __syncthreads();
        }
        if (l < NCB) {
            int excl = sm.sc.cS[l] - c;
            int epos = sm.sc.eS[l] - e;
            g_offsets[l] = excl;
            if (l == NCB - 1) { g_offsets[NCB] = sm.sc.cS[l]; g_nwork = sm.sc.eS[l]; }
            for (int i = 0; i < e; i++) {
                int st = i * PPB;
                g_worklist[epos + i] = make_int4(l, excl + st, min(PPB, c - st), 0);
            }
        }
    }
}

// ---------------- K5: scatter — NO atomics ----------------
__global__ void k_scatter() {
    __shared__ int offS[NCB];
    int tid = threadIdx.x;
    if (tid < NCB) offS[tid] = g_offsets[tid];
    __syncthreads();
    int n = blockIdx.x * 256 + tid;
    int lp = g_lp[n];
    g_perm[offS[lp & 63] + (lp >> 6)] = n;
}

// ---------------- K6: main PQ — 64 thr, 4 contiguous pts/thread ----------------
__global__ void __launch_bounds__(64, 4) k_main() {
    __shared__ __align__(16) u64 ckS[2][128 * DSUB];  // 2 x 16 KB
    __shared__ __align__(16) u64 cn2S[2][128];
    int bid = blockIdx.x;
    if (bid >= g_nwork) return;
    int4 w = g_worklist[bid];
    int label = w.x, start = w.y, cnt = w.z;
    int tid = threadIdx.x;

    const char* tbase = (const char*)(g_ckPair + (size_t)label * NSUB * 128 * DSUB);
    const char* cbase = (const char*)(g_cn2 + label * NSUB * 128);

    int base = 4 * tid;
    bool act = (base < cnt);
    bool v0 = act, v1 = (base + 1 < cnt), v2 = (base + 2 < cnt), v3 = (base + 3 < cnt);
    int p0 = g_perm[start + (v0 ? base : 0)];
    int p1 = g_perm[start + (v1 ? base + 1 : 0)];
    int p2 = g_perm[start + (v2 ? base + 2 : 0)];
    int p3 = g_perm[start + (v3 ? base + 3 : 0)];
    u64 codeA = 0, codeB = 0, codeC = 0, codeD = 0;

    {
        char* td = (char*)ckS[0];
        #pragma unroll
        for (int i = 0; i < 16; i++)
            cpa16(td + tid * 16 + i * 1024, tbase + tid * 16 + i * 1024);
        cpa16((char*)cn2S[0] + tid * 16, cbase + tid * 16);
        cpa_commit();
    }

    for (int s = 0; s < NSUB; s++) {
        int cur = s & 1;

        float4 a0, a1, a2, a3, b0, b1, b2, b3, c0, c1, c2, c3, e0, e1, e2, e3;
        if (act) {
            const float4* xr0 = (const float4*)(g_xT + (size_t)p0 * DVEC + s * DSUB);
            const float4* xr1 = (const float4*)(g_xT + (size_t)p1 * DVEC + s * DSUB);
            const float4* xr2 = (const float4*)(g_xT + (size_t)p2 * DVEC + s * DSUB);
            const float4* xr3 = (const float4*)(g_xT + (size_t)p3 * DVEC + s * DSUB);
            a0 = xr0[0]; a1 = xr0[1]; a2 = xr0[2]; a3 = xr0[3];
            b0 = xr1[0]; b1 = xr1[1]; b2 = xr1[2]; b3 = xr1[3];
            c0 = xr2[0]; c1 = xr2[1]; c2 = xr2[2]; c3 = xr2[3];
            e0 = xr3[0]; e1 = xr3[1]; e2 = xr3[2]; e3 = xr3[3];
        }

        cpa_wait0();
        __syncthreads();

        if (s < NSUB - 1) {
            char* td = (char*)ckS[cur ^ 1];
            const char* ts = tbase + (size_t)(s + 1) * 128 * DSUB * 8;
            #pragma unroll
            for (int i = 0; i < 16; i++)
                cpa16(td + tid * 16 + i * 1024, ts + tid * 16 + i * 1024);
            cpa16((char*)cn2S[cur ^ 1] + tid * 16, cbase + (size_t)(s + 1) * 128 * 8 + tid * 16);
            cpa_commit();
        }

        if (act) {
            u64 xA[16], xB[16], xC[16], xD[16];
            xA[0]=pk2(a0.x,a0.x); xA[1]=pk2(a0.y,a0.y); xA[2]=pk2(a0.z,a0.z); xA[3]=pk2(a0.w,a0.w);
            xA[4]=pk2(a1.x,a1.x); xA[5]=pk2(a1.y,a1.y); xA[6]=pk2(a1.z,a1.z); xA[7]=pk2(a1.w,a1.w);
            xA[8]=pk2(a2.x,a2.x); xA[9]=pk2(a2.y,a2.y); xA[10]=pk2(a2.z,a2.z); xA[11]=pk2(a2.w,a2.w);
            xA[12]=pk2(a3.x,a3.x); xA[13]=pk2(a3.y,a3.y); xA[14]=pk2(a3.z,a3.z); xA[15]=pk2(a3.w,a3.w);
            xB[0]=pk2(b0.x,b0.x); xB[1]=pk2(b0.y,b0.y); xB[2]=pk2(b0.z,b0.z); xB[3]=pk2(b0.w,b0.w);
            xB[4]=pk2(b1.x,b1.x); xB[5]=pk2(b1.y,b1.y); xB[6]=pk2(b1.z,b1.z); xB[7]=pk2(b1.w,b1.w);
            xB[8]=pk2(b2.x,b2.x); xB[9]=pk2(b2.y,b2.y); xB[10]=pk2(b2.z,b2.z); xB[11]=pk2(b2.w,b2.w);
            xB[12]=pk2(b3.x,b3.x); xB[13]=pk2(b3.y,b3.y); xB[14]=pk2(b3.z,b3.z); xB[15]=pk2(b3.w,b3.w);
            xC[0]=pk2(c0.x,c0.x); xC[1]=pk2(c0.y,c0.y); xC[2]=pk2(c0.z,c0.z); xC[3]=pk2(c0.w,c0.w);
            xC[4]=pk2(c1.x,c1.x); xC[5]=pk2(c1.y,c1.y); xC[6]=pk2(c1.z,c1.z); xC[7]=pk2(c1.w,c1.w);
            xC[8]=pk2(c2.x,c2.x); xC[9]=pk2(c2.y,c2.y); xC[10]=pk2(c2.z,c2.z); xC[11]=pk2(c2.w,c2.w);
            xC[12]=pk2(c3.x,c3.x); xC[13]=pk2(c3.y,c3.y); xC[14]=pk2(c3.z,c3.z); xC[15]=pk2(c3.w,c3.w);
            xD[0]=pk2(e0.x,e0.x); xD[1]=pk2(e0.y,e0.y); xD[2]=pk2(e0.z,e0.z); xD[3]=pk2(e0.w,e0.w);
            xD[4]=pk2(e1.x,e1.x); xD[5]=pk2(e1.y,e1.y); xD[6]=pk2(e1.z,e1.z); xD[7]=pk2(e1.w,e1.w);
            xD[8]=pk2(e2.x,e2.x); xD[9]=pk2(e2.y,e2.y); xD[10]=pk2(e2.z,e2.z); xD[11]=pk2(e2.w,e2.w);
            xD[12]=pk2(e3.x,e3.x); xD[13]=pk2(e3.y,e3.y); xD[14]=pk2(e3.z,e3.z); xD[15]=pk2(e3.w,e3.w);

            float bestA = -3.4e38f, bestB = -3.4e38f, bestC = -3.4e38f, bestD = -3.4e38f;
            int kA = 0, kB = 0, kC = 0, kD = 0;

            const u64* tile = ckS[cur];
            const u64* cn2t = cn2S[cur];

            for (int p = 0; p < 128; p++) {
                const ulonglong2* cr = (const ulonglong2*)(tile + p * DSUB);
                u64 cn2 = cn2t[p];
                ulonglong2 q0 = cr[0], q1 = cr[1], q2 = cr[2], q3 = cr[3];
                u64 aA = ffma2(xA[0], q0.x, cn2);
                u64 aB = ffma2(xB[0], q0.x, cn2);
                u64 aC = ffma2(xC[0], q0.x, cn2);
                u64 aD = ffma2(xD[0], q0.x, cn2);
                aA = ffma2(xA[1], q0.y, aA);  aB = ffma2(xB[1], q0.y, aB);  aC = ffma2(xC[1], q0.y, aC);  aD = ffma2(xD[1], q0.y, aD);
                aA = ffma2(xA[2], q1.x, aA);  aB = ffma2(xB[2], q1.x, aB);  aC = ffma2(xC[2], q1.x, aC);  aD = ffma2(xD[2], q1.x, aD);
                aA = ffma2(xA[3], q1.y, aA);  aB = ffma2(xB[3], q1.y, aB);  aC = ffma2(xC[3], q1.y, aC);  aD = ffma2(xD[3], q1.y, aD);
                aA = ffma2(xA[4], q2.x, aA);  aB = ffma2(xB[4], q2.x, aB);  aC = ffma2(xC[4], q2.x, aC);  aD = ffma2(xD[4], q2.x, aD);
                aA = ffma2(xA[5], q2.y, aA);  aB = ffma2(xB[5], q2.y, aB);  aC = ffma2(xC[5], q2.y, aC);  aD = ffma2(xD[5], q2.y, aD);
                aA = ffma2(xA[6], q3.x, aA);  aB = ffma2(xB[6], q3.x, aB);  aC = ffma2(xC[6], q3.x, aC);  aD = ffma2(xD[6], q3.x, aD);
                aA = ffma2(xA[7], q3.y, aA);  aB = ffma2(xB[7], q3.y, aB);  aC = ffma2(xC[7], q3.y, aC);  aD = ffma2(xD[7], q3.y, aD);
                ulonglong2 q4 = cr[4], q5 = cr[5], q6 = cr[6], q7 = cr[7];
                aA = ffma2(xA[8],  q4.x, aA);  aB = ffma2(xB[8],  q4.x, aB);  aC = ffma2(xC[8],  q4.x, aC);  aD = ffma2(xD[8],  q4.x, aD);
                aA = ffma2(xA[9],  q4.y, aA);  aB = ffma2(xB[9],  q4.y, aB);  aC = ffma2(xC[9],  q4.y, aC);  aD = ffma2(xD[9],  q4.y, aD);
                aA = ffma2(xA[10], q5.x, aA);  aB = ffma2(xB[10], q5.x, aB);  aC = ffma2(xC[10], q5.x, aC);  aD = ffma2(xD[10], q5.x, aD);
                aA = ffma2(xA[11], q5.y, aA);  aB = ffma2(xB[11], q5.y, aB);  aC = ffma2(xC[11], q5.y, aC);  aD = ffma2(xD[11], q5.y, aD);
                aA = ffma2(xA[12], q6.x, aA);  aB = ffma2(xB[12], q6.x, aB);  aC = ffma2(xC[12], q6.x, aC);  aD = ffma2(xD[12], q6.x, aD);
                aA = ffma2(xA[13], q6.y, aA);  aB = ffma2(xB[13], q6.y, aB);  aC = ffma2(xC[13], q6.y, aC);  aD = ffma2(xD[13], q6.y, aD);
                aA = ffma2(xA[14], q7.x, aA);  aB = ffma2(xB[14], q7.x, aB);  aC = ffma2(xC[14], q7.x, aC);  aD = ffma2(xD[14], q7.x, aD);
                aA = ffma2(xA[15], q7.y, aA);  aB = ffma2(xB[15], q7.y, aB);  aC = ffma2(xC[15], q7.y, aC);  aD = ffma2(xD[15], q7.y, aD);

                float sA0, sA1, sB0, sB1, sC0, sC1, sD0, sD1;
                unpk2(aA, sA0, sA1); unpk2(aB, sB0, sB1); unpk2(aC, sC0, sC1); unpk2(aD, sD0, sD1);
                if (sA0 > bestA) { bestA = sA0; kA = 2 * p; }
                if (sA1 > bestA) { bestA = sA1; kA = 2 * p + 1; }
                if (sB0 > bestB) { bestB = sB0; kB = 2 * p; }
                if (sB1 > bestB) { bestB = sB1; kB = 2 * p + 1; }
                if (sC0 > bestC) { bestC = sC0; kC = 2 * p; }
                if (sC1 > bestC) { bestC = sC1; kC = 2 * p + 1; }
                if (sD0 > bestD) { bestD = sD0; kD = 2 * p; }
                if (sD1 > bestD) { bestD = sD1; kD = 2 * p + 1; }
            }

            codeA |= ((u64)kA) << (8 * s);
            codeB |= ((u64)kB) << (8 * s);
            codeC |= ((u64)kC) << (8 * s);
            codeD |= ((u64)kD) << (8 * s);
        }
    }
    if (v0) g_codes[p0] = codeA;
    if (v1) g_codes[p1] = codeB;
    if (v2) g_codes[p2] = codeC;
    if (v3) g_codes[p3] = codeD;
}

// ---------------- K7: decode — 2 pts/thread, float2 stores ----------------
__global__ void k_decode(float* __restrict__ out) {
    int t = blockIdx.x * 256 + threadIdx.x;
    int n = 2 * t;
    int lab0 = g_lp[n] & 63, lab1 = g_lp[n + 1] & 63;
    u64 cd0 = g_codes[n], cd1 = g_codes[n + 1];

    #pragma unroll
    for (int s = 0; s < NSUB; s++) {
        const float4* c0 = (const float4*)(g_ckPack + ((size_t)(lab0 * NSUB + s) * KCLUS + (int)((cd0 >> (8 * s)) & 255)) * DSUB);
        const float4* c1 = (const float4*)(g_ckPack + ((size_t)(lab1 * NSUB + s) * KCLUS + (int)((cd1 >> (8 * s)) & 255)) * DSUB);
        #pragma unroll
        for (int j = 0; j < 4; j++) {
            float4 v0 = c0[j], v1 = c1[j];
            size_t b = (size_t)(s * DSUB + 4 * j) * N_DATA + n;
            *(float2*)(out + b)              = make_float2(v0.x, v1.x);
            *(float2*)(out + b + N_DATA)     = make_float2(v0.y, v1.y);
            *(float2*)(out + b + 2 * N_DATA) = make_float2(v0.z, v1.z);
            *(float2*)(out + b + 3 * N_DATA) = make_float2(v0.w, v1.w);
        }
    }
}

// ---------------- launch ----------------
extern "C" void kernel_launch(void* const* d_in, const int* in_sizes, int n_in,
                              void* d_out, int out_size) {
    const float* x   = (const float*)d_in[0];
    const float* cb  = (const float*)d_in[1];
    const float* sel = (const float*)d_in[2];
    float* out = (float*)d_out;

    k_selpack<<<1, 256>>>(sel);
    k_labelpack<<<NLABBLK + NCB * NSUB, 256>>>(x, cb);
    k_scatter<<<N_DATA / 256, 256>>>();
    k_main<<<MAXWORK, 64>>>();
    k_decode<<<N_DATA / 512, 256>>>(out);
}